// round 10
// baseline (speedup 1.0000x reference)
#include <cuda_runtime.h>
#include <cuda_bf16.h>
#include <mma.h>
#include <cstdint>

using namespace nvcuda;

#define Nn 50000
#define Ee 800000
#define Dd 128
#define Hh 256
#define Tt 10000
#define EPSV 1e-5f
#define SCAN_BLOCKS 196
#define NPAD 50048   // 782 * 64

// ---------------- scratch ----------------
__device__ float g_disqrt[Nn];
__device__ int   g_cnt[Nn];
__device__ int   g_off[Nn + 1];
__device__ int   g_cursor[Nn];
__device__ int   g_bsum[SCAN_BLOCKS];
__device__ int   g_csrc[Ee];
__device__ float g_cnorm[Ee];
__device__ float g_hw[(size_t)NPAD * Hh];      // activations ping
__device__ float g_hw2[(size_t)NPAD * Hh];     // activations pong
__device__ float g_stats4[4][2 * Hh];          // per-layer [sum|sumsq]
__device__ __nv_bfloat16 g_ghi[(size_t)Tt * Hh];
__device__ __nv_bfloat16 g_glo[(size_t)Tt * Hh];
__device__ __nv_bfloat16 g_whi[4 * Hh * Hh];
__device__ __nv_bfloat16 g_wlo[4 * Hh * Hh];

// ---------------- helpers ----------------
__device__ __forceinline__ void cp16(uint32_t dst, const void* src, int bytes) {
    asm volatile("cp.async.cg.shared.global [%0], [%1], 16, %2;"
                 :: "r"(dst), "l"(src), "r"(bytes) : "memory");
}
#define CP_COMMIT() asm volatile("cp.async.commit_group;" ::: "memory")
#define CP_WAIT1()  asm volatile("cp.async.wait_group 1;" ::: "memory")
#define CP_WAIT0()  asm volatile("cp.async.wait_group 0;" ::: "memory")

// ---------------- graph preprocessing ----------------
__global__ void k_zero_init() {
    int i = blockIdx.x * blockDim.x + threadIdx.x;
    if (i < Nn) g_cnt[i] = 0;
    if (i < 4 * 2 * Hh) ((float*)g_stats4)[i] = 0.0f;
}
__global__ void k_count(const int* __restrict__ row) {
    int e = blockIdx.x * blockDim.x + threadIdx.x;
    if (e < Ee) atomicAdd(&g_cnt[row[e]], 1);
}
__global__ void k_scan1() {
    int t = threadIdx.x, b = blockIdx.x;
    int i = b * 256 + t;
    int v = (i < Nn) ? g_cnt[i] : 0;
    if (i < Nn) g_disqrt[i] = rsqrtf((float)v + 1.0f);
    int lane = t & 31, w = t >> 5;
    int x = v;
#pragma unroll
    for (int o = 1; o < 32; o <<= 1) {
        int y = __shfl_up_sync(0xffffffffu, x, o);
        if (lane >= o) x += y;
    }
    __shared__ int wsum[8];
    if (lane == 31) wsum[w] = x;
    __syncthreads();
    if (w == 0) {
        int s = (lane < 8) ? wsum[lane] : 0;
#pragma unroll
        for (int o = 1; o < 8; o <<= 1) {
            int y = __shfl_up_sync(0xffffffffu, s, o);
            if (lane >= o) s += y;
        }
        if (lane < 8) wsum[lane] = s;
    }
    __syncthreads();
    int incl = x + (w > 0 ? wsum[w - 1] : 0);
    if (i < Nn) g_off[i] = incl - v;
    if (t == 255) g_bsum[b] = incl;
}
__global__ void k_scan2() {
    int t = threadIdx.x;
    int v = (t < SCAN_BLOCKS) ? g_bsum[t] : 0;
    int lane = t & 31, w = t >> 5;
    int x = v;
#pragma unroll
    for (int o = 1; o < 32; o <<= 1) {
        int y = __shfl_up_sync(0xffffffffu, x, o);
        if (lane >= o) x += y;
    }
    __shared__ int wsum[8];
    if (lane == 31) wsum[w] = x;
    __syncthreads();
    if (w == 0) {
        int s = (lane < 8) ? wsum[lane] : 0;
#pragma unroll
        for (int o = 1; o < 8; o <<= 1) {
            int y = __shfl_up_sync(0xffffffffu, s, o);
            if (lane >= o) s += y;
        }
        if (lane < 8) wsum[lane] = s;
    }
    __syncthreads();
    int incl = x + (w > 0 ? wsum[w - 1] : 0);
    if (t < SCAN_BLOCKS) g_bsum[t] = incl - v;
}
__global__ void k_scan3() {
    int t = threadIdx.x, b = blockIdx.x;
    int i = b * 256 + t;
    if (i < Nn) {
        int off = g_off[i] + g_bsum[b];
        g_off[i] = off;
        g_cursor[i] = off;
    }
    if (i == 0) g_off[Nn] = Ee;
}
__global__ void k_scatter(const int* __restrict__ row, const int* __restrict__ col) {
    int e = blockIdx.x * blockDim.x + threadIdx.x;
    if (e < Ee) {
        int d = row[e];
        int s = col[e];
        int pos = atomicAdd(&g_cursor[d], 1);
        g_csrc[pos] = s;
        g_cnorm[pos] = g_disqrt[d] * g_disqrt[s];
    }
}

// ---------------- all-weights bf16 split ----------------
__global__ void k_wsplit_all(const float* __restrict__ W1, const float* __restrict__ W2,
                             const float* __restrict__ W3, const float* __restrict__ Wl) {
    int idx = blockIdx.x * blockDim.x + threadIdx.x;
    const int S1 = Dd * Hh;
    const int SW = Hh * Hh;
    const int total = S1 + 3 * SW;
    if (idx >= total) return;
    const float* src;
    int dofs;
    if (idx < S1) { src = W1 + idx; dofs = idx; }
    else {
        int r = idx - S1;
        int which = r / SW, o = r % SW;
        src = (which == 0 ? W2 : which == 1 ? W3 : Wl) + o;
        dofs = (which + 1) * SW + o;
    }
    float v = *src;
    __nv_bfloat16 h = __float2bfloat16_rn(v);
    g_whi[dofs] = h;
    g_wlo[dofs] = __float2bfloat16_rn(v - __bfloat162float(h));
}

// ---------------- fused agg(+BN+ReLU) + 3xBF16 GEMM + stats ----------------
// Block: 64 dest rows x 256 N. src and C are DIFFERENT buffers (ping-pong) —
// blocks gather arbitrary src rows, so in-place is a race (R9 lesson).
#define FALD 72    // 64 + 8
#define FBLD 264   // 256 + 8
#define SMEM_FUSED ((2 * 64 * FALD + 2 * 64 * FBLD) * 2)  // 86016 bytes

using AFrag = wmma::fragment<wmma::matrix_a, 16, 16, 16, __nv_bfloat16, wmma::row_major>;
using BFrag = wmma::fragment<wmma::matrix_b, 16, 16, 16, __nv_bfloat16, wmma::row_major>;
using CFrag = wmma::fragment<wmma::accumulator, 16, 16, 16, float>;

template <int KC, bool BN>
__global__ __launch_bounds__(256, 2) void k_fused(
    const float* __restrict__ src,        // [Nn][KC] fp32 activations (or x)
    const float* __restrict__ stats_in,   // prev-layer [sum|sumsq] (BN only)
    const float* __restrict__ gamma, const float* __restrict__ beta,
    const __nv_bfloat16* __restrict__ Whi, const __nv_bfloat16* __restrict__ Wlo, // [KC][256]
    float* __restrict__ C, float* __restrict__ stats_out) {
    extern __shared__ __nv_bfloat16 sm[];
    __nv_bfloat16* AH = sm;                       // [64][FALD]
    __nv_bfloat16* AL = AH + 64 * FALD;
    __nv_bfloat16* BH = AL + 64 * FALD;           // [64][FBLD]
    __nv_bfloat16* BL = BH + 64 * FBLD;

    const int tid = threadIdx.x;
    const int wid = tid >> 5;
    const int lane = tid & 31;
    const int rowBase = blockIdx.x * 64;
    const int wm = wid & 1;    // 2 warps over M (32 rows)
    const int wn = wid >> 1;   // 4 warps over N (64 cols)

    CFrag c[2][4];
#pragma unroll
    for (int i = 0; i < 2; i++)
#pragma unroll
        for (int j = 0; j < 4; j++) wmma::fill_fragment(c[i][j], 0.0f);

    const float invN = 1.0f / (float)Nn;

#pragma unroll
    for (int cc = 0; cc < KC / 64; cc++) {
        const int k0 = cc * 64;
        // --- issue B chunk cp.async (hides under aggregation) ---
#pragma unroll
        for (int t = 0; t < 8; t++) {
            int id = tid + t * 256;         // 0..2047
            int kr = id >> 5;               // 0..63
            int nc = (id & 31) * 8;         // 0..248
            size_t g = (size_t)(k0 + kr) * Hh + nc;
            cp16((uint32_t)__cvta_generic_to_shared(BH + (size_t)kr * FBLD + nc), Whi + g, 16);
            cp16((uint32_t)__cvta_generic_to_shared(BL + (size_t)kr * FBLD + nc), Wlo + g, 16);
        }
        CP_COMMIT();

        // --- BN scale/shift for this lane's 2 columns ---
        float sc0 = 1.f, sc1 = 1.f, sh0 = 0.f, sh1 = 0.f;
        if (BN) {
            int j0 = k0 + lane * 2;
            float mu0 = stats_in[j0] * invN;
            float var0 = fmaxf(stats_in[Hh + j0] * invN - mu0 * mu0, 0.0f);
            sc0 = gamma[j0] * rsqrtf(var0 + EPSV);
            sh0 = beta[j0] - mu0 * sc0;
            float mu1 = stats_in[j0 + 1] * invN;
            float var1 = fmaxf(stats_in[Hh + j0 + 1] * invN - mu1 * mu1, 0.0f);
            sc1 = gamma[j0 + 1] * rsqrtf(var1 + EPSV);
            sh1 = beta[j0 + 1] - mu1 * sc1;
        }

        // --- aggregate 8 rows per warp (64 rows total), 2 cols per lane ---
#pragma unroll 1
        for (int rr = 0; rr < 8; rr++) {
            int r = wid * 8 + rr;
            int grow = rowBase + r;
            float a0 = 0.f, a1 = 0.f;
            if (grow < Nn) {
                float dsq = g_disqrt[grow];
                float sl = dsq * dsq;
                float2 v = *(const float2*)(src + (size_t)grow * KC + k0 + lane * 2);
                float u0 = BN ? fmaxf(fmaf(v.x, sc0, sh0), 0.0f) : v.x;
                float u1 = BN ? fmaxf(fmaf(v.y, sc1, sh1), 0.0f) : v.y;
                a0 = u0 * sl;
                a1 = u1 * sl;
                int e0 = g_off[grow], e1 = g_off[grow + 1];
                for (int e = e0; e < e1; e++) {
                    int s = g_csrc[e];
                    float nm = g_cnorm[e];
                    float2 w = *(const float2*)(src + (size_t)s * KC + k0 + lane * 2);
                    float t0 = BN ? fmaxf(fmaf(w.x, sc0, sh0), 0.0f) : w.x;
                    float t1 = BN ? fmaxf(fmaf(w.y, sc1, sh1), 0.0f) : w.y;
                    a0 = fmaf(t0, nm, a0);
                    a1 = fmaf(t1, nm, a1);
                }
            }
            __nv_bfloat16 h0 = __float2bfloat16_rn(a0);
            __nv_bfloat16 h1 = __float2bfloat16_rn(a1);
            float l0 = a0 - __bfloat162float(h0);
            float l1 = a1 - __bfloat162float(h1);
            *(__nv_bfloat162*)(AH + (size_t)r * FALD + lane * 2) =
                __halves2bfloat162(h0, h1);
            *(__nv_bfloat162*)(AL + (size_t)r * FALD + lane * 2) =
                __floats2bfloat162_rn(l0, l1);
        }

        CP_WAIT0();
        __syncthreads();

        // --- MMA over 4 k-steps of 16 ---
#pragma unroll
        for (int ks = 0; ks < 4; ks++) {
            AFrag ah[2], al[2];
            BFrag bh[4], bl[4];
#pragma unroll
            for (int i = 0; i < 2; i++) {
                const __nv_bfloat16* pa = AH + (size_t)(wm * 32 + i * 16) * FALD + ks * 16;
                wmma::load_matrix_sync(ah[i], pa, FALD);
                wmma::load_matrix_sync(al[i], pa + 64 * FALD, FALD);
            }
#pragma unroll
            for (int j = 0; j < 4; j++) {
                const __nv_bfloat16* pb = BH + (size_t)(ks * 16) * FBLD + wn * 64 + j * 16;
                wmma::load_matrix_sync(bh[j], pb, FBLD);
                wmma::load_matrix_sync(bl[j], pb + 64 * FBLD, FBLD);
            }
#pragma unroll
            for (int i = 0; i < 2; i++)
#pragma unroll
                for (int j = 0; j < 4; j++) {
                    wmma::mma_sync(c[i][j], ah[i], bh[j], c[i][j]);
                    wmma::mma_sync(c[i][j], ah[i], bl[j], c[i][j]);
                    wmma::mma_sync(c[i][j], al[i], bh[j], c[i][j]);
                }
        }
        __syncthreads();
    }

    // --- store C ---
#pragma unroll
    for (int i = 0; i < 2; i++)
#pragma unroll
        for (int j = 0; j < 4; j++) {
            int grow = rowBase + wm * 32 + i * 16;
            wmma::store_matrix_sync(C + (size_t)grow * Hh + wn * 64 + j * 16,
                                    c[i][j], Hh, wmma::mem_row_major);
        }

    // --- fused BN stats ---
    if (stats_out) {
        float* ct = (float*)sm;   // 64 x 260 fp32 (mainloop smem dead)
#pragma unroll
        for (int i = 0; i < 2; i++)
#pragma unroll
            for (int j = 0; j < 4; j++)
                wmma::store_matrix_sync(ct + (size_t)(wm * 32 + i * 16) * 260 + wn * 64 + j * 16,
                                        c[i][j], 260, wmma::mem_row_major);
        __syncthreads();
        float s = 0.f, s2 = 0.f;
        const float* p = ct + tid;
#pragma unroll 8
        for (int r = 0; r < 64; r++) {
            float v = p[(size_t)r * 260];
            s += v;
            s2 = fmaf(v, v, s2);
        }
        atomicAdd(&stats_out[tid], s);
        atomicAdd(&stats_out[Hh + tid], s2);
    }
}

// ---------------- head GEMM (10000 rows): 3xBF16, cp.async ----------------
#define GBK 32
#define ALD 40
#define BLD 136
#define SMEM_GEMM ((2 * 128 * ALD * 2 + 2 * GBK * BLD * 2) * 2)

__global__ __launch_bounds__(256) void k_gemm(const __nv_bfloat16* __restrict__ Ahi,
                                              const __nv_bfloat16* __restrict__ Alo,
                                              const __nv_bfloat16* __restrict__ Bhi,
                                              const __nv_bfloat16* __restrict__ Blo,
                                              float* __restrict__ C, int M, int K) {
    extern __shared__ __nv_bfloat16 sm[];
    __nv_bfloat16* AH = sm;
    __nv_bfloat16* AL = AH + 2 * 128 * ALD;
    __nv_bfloat16* BH = AL + 2 * 128 * ALD;
    __nv_bfloat16* BL = BH + 2 * GBK * BLD;

    const int tid = threadIdx.x;
    const int warp = tid >> 5;
    const int rowBase = blockIdx.y * 128;
    const int colBase = blockIdx.x * 128;
    const int wm = warp & 3;
    const int wn = warp >> 2;

    CFrag c[2][4];
#pragma unroll
    for (int i = 0; i < 2; i++)
#pragma unroll
        for (int j = 0; j < 4; j++) wmma::fill_fragment(c[i][j], 0.0f);

    auto load_stage = [&](int buf, int k0) {
#pragma unroll
        for (int t = 0; t < 2; t++) {
            int id = tid + t * 256;
            int r = id >> 2;
            int cc = (id & 3) * 8;
            int grow = rowBase + r;
            size_t gofs = (size_t)(grow < M ? grow : 0) * K + k0 + cc;
            int bytes = grow < M ? 16 : 0;
            cp16((uint32_t)__cvta_generic_to_shared(AH + ((size_t)buf * 128 + r) * ALD + cc),
                 Ahi + gofs, bytes);
            cp16((uint32_t)__cvta_generic_to_shared(AL + ((size_t)buf * 128 + r) * ALD + cc),
                 Alo + gofs, bytes);
        }
#pragma unroll
        for (int t = 0; t < 2; t++) {
            int id = tid + t * 256;
            int kr = id >> 4;
            int nc = (id & 15) * 8;
            size_t gofs = (size_t)(k0 + kr) * Hh + colBase + nc;
            cp16((uint32_t)__cvta_generic_to_shared(BH + ((size_t)buf * GBK + kr) * BLD + nc),
                 Bhi + gofs, 16);
            cp16((uint32_t)__cvta_generic_to_shared(BL + ((size_t)buf * GBK + kr) * BLD + nc),
                 Blo + gofs, 16);
        }
    };

    const int NC = K >> 5;
    load_stage(0, 0);
    CP_COMMIT();

    for (int cidx = 0; cidx < NC; cidx++) {
        int buf = cidx & 1;
        if (cidx + 1 < NC) {
            load_stage(buf ^ 1, (cidx + 1) << 5);
            CP_COMMIT();
            CP_WAIT1();
        } else {
            CP_WAIT0();
        }
        __syncthreads();

#pragma unroll
        for (int ks = 0; ks < 2; ks++) {
            AFrag ah[2], al[2];
            BFrag bh[4], bl[4];
#pragma unroll
            for (int i = 0; i < 2; i++) {
                const __nv_bfloat16* pa = AH + ((size_t)buf * 128 + wm * 32 + i * 16) * ALD + ks * 16;
                wmma::load_matrix_sync(ah[i], pa, ALD);
                wmma::load_matrix_sync(al[i], pa + 2 * 128 * ALD, ALD);
            }
#pragma unroll
            for (int j = 0; j < 4; j++) {
                const __nv_bfloat16* pb = BH + ((size_t)buf * GBK + ks * 16) * BLD + wn * 64 + j * 16;
                wmma::load_matrix_sync(bh[j], pb, BLD);
                wmma::load_matrix_sync(bl[j], pb + 2 * GBK * BLD, BLD);
            }
#pragma unroll
            for (int i = 0; i < 2; i++)
#pragma unroll
                for (int j = 0; j < 4; j++) {
                    wmma::mma_sync(c[i][j], ah[i], bh[j], c[i][j]);
                    wmma::mma_sync(c[i][j], ah[i], bl[j], c[i][j]);
                    wmma::mma_sync(c[i][j], al[i], bh[j], c[i][j]);
                }
        }
        __syncthreads();
    }

#pragma unroll
    for (int i = 0; i < 2; i++)
#pragma unroll
        for (int j = 0; j < 4; j++) {
            int grow = rowBase + wm * 32 + i * 16;
            wmma::store_matrix_sync(C + (size_t)grow * Hh + colBase + wn * 64 + j * 16,
                                    c[i][j], Hh, wmma::mem_row_major);
        }
}

// ---------------- head: gather + BN3 + relu + bf16 split ----------------
__global__ void k_gather_bn(const float* __restrict__ hsrc,
                            const int* __restrict__ train, const float* __restrict__ stats,
                            const float* __restrict__ gamma, const float* __restrict__ beta) {
    int idx = blockIdx.x * blockDim.x + threadIdx.x;
    if (idx >= Tt * 64) return;
    int t = idx >> 6, cq = idx & 63;
    int node = train[t];
    float4 v = ((const float4*)hsrc)[(size_t)node * 64 + cq];
    const float invN = 1.0f / (float)Nn;
    float tv[4] = {v.x, v.y, v.z, v.w};
    float h[4], l[4];
#pragma unroll
    for (int k = 0; k < 4; k++) {
        int j = cq * 4 + k;
        float mu = stats[j] * invN;
        float var = fmaxf(stats[Hh + j] * invN - mu * mu, 0.0f);
        float sc = gamma[j] * rsqrtf(var + EPSV);
        float u = fmaxf(fmaf(tv[k], sc, beta[j] - mu * sc), 0.0f);
        __nv_bfloat16 hb = __float2bfloat16_rn(u);
        h[k] = __bfloat162float(hb);
        l[k] = u - h[k];
    }
    size_t base = (size_t)t * Hh + cq * 4;
    *(__nv_bfloat162*)(g_ghi + base) = __floats2bfloat162_rn(h[0], h[1]);
    *(__nv_bfloat162*)(g_ghi + base + 2) = __floats2bfloat162_rn(h[2], h[3]);
    *(__nv_bfloat162*)(g_glo + base) = __floats2bfloat162_rn(l[0], l[1]);
    *(__nv_bfloat162*)(g_glo + base + 2) = __floats2bfloat162_rn(l[2], l[3]);
}

__global__ void k_out(const float* __restrict__ hsrc,
                      const float* __restrict__ bl, const float* __restrict__ Wf,
                      const float* __restrict__ bf, float* __restrict__ out) {
    int warp = (blockIdx.x * blockDim.x + threadIdx.x) >> 5;
    int lane = threadIdx.x & 31;
    if (warp >= Tt) return;
    float acc = 0.f;
    const float* hp = hsrc + (size_t)warp * Hh;
#pragma unroll
    for (int j0 = 0; j0 < Hh; j0 += 32) {
        int j = j0 + lane;
        float v = fmaxf(hp[j] + bl[j], 0.0f);
        acc = fmaf(v, Wf[j], acc);
    }
#pragma unroll
    for (int o = 16; o > 0; o >>= 1) acc += __shfl_xor_sync(0xffffffffu, acc, o);
    if (lane == 0) out[warp] = acc + bf[0];
}

// ---------------- launch ----------------
extern "C" void kernel_launch(void* const* d_in, const int* in_sizes, int n_in,
                              void* d_out, int out_size) {
    const float* x = (const float*)d_in[0];
    const int* ei = (const int*)d_in[1];
    const int* train = (const int*)d_in[2];
    const float* W1 = (const float*)d_in[3];
    const float* W2 = (const float*)d_in[5];
    const float* W3 = (const float*)d_in[7];
    const float* g1 = (const float*)d_in[9];
    const float* be1 = (const float*)d_in[10];
    const float* g2 = (const float*)d_in[11];
    const float* be2 = (const float*)d_in[12];
    const float* g3 = (const float*)d_in[13];
    const float* be3 = (const float*)d_in[14];
    const float* Wl = (const float*)d_in[15];
    const float* bl = (const float*)d_in[16];
    const float* Wf = (const float*)d_in[17];
    const float* bf = (const float*)d_in[18];
    float* out = (float*)d_out;

    const int* row = ei;
    const int* col = ei + Ee;

    float *p_hw, *p_hw2, *p_stats;
    __nv_bfloat16 *p_ghi, *p_glo, *p_whi, *p_wlo;
    cudaGetSymbolAddress((void**)&p_hw, g_hw);
    cudaGetSymbolAddress((void**)&p_hw2, g_hw2);
    cudaGetSymbolAddress((void**)&p_stats, g_stats4);
    cudaGetSymbolAddress((void**)&p_ghi, g_ghi);
    cudaGetSymbolAddress((void**)&p_glo, g_glo);
    cudaGetSymbolAddress((void**)&p_whi, g_whi);
    cudaGetSymbolAddress((void**)&p_wlo, g_wlo);

    cudaFuncSetAttribute(k_fused<128, false>, cudaFuncAttributeMaxDynamicSharedMemorySize, SMEM_FUSED);
    cudaFuncSetAttribute(k_fused<256, true>, cudaFuncAttributeMaxDynamicSharedMemorySize, SMEM_FUSED);
    cudaFuncSetAttribute(k_gemm, cudaFuncAttributeMaxDynamicSharedMemorySize, SMEM_GEMM);

    // ---- graph preprocessing ----
    k_zero_init<<<(Nn + 255) / 256, 256>>>();
    k_count<<<(Ee + 255) / 256, 256>>>(row);
    k_scan1<<<SCAN_BLOCKS, 256>>>();
    k_scan2<<<1, 256>>>();
    k_scan3<<<SCAN_BLOCKS, 256>>>();
    k_scatter<<<(Ee + 255) / 256, 256>>>(row, col);
    k_wsplit_all<<<(Dd * Hh + 3 * Hh * Hh + 255) / 256, 256>>>(W1, W2, W3, Wl);

    const int fused_blocks = NPAD / 64;   // 782
    float* st0 = p_stats + 0 * 2 * Hh;
    float* st1 = p_stats + 1 * 2 * Hh;
    float* st2 = p_stats + 2 * 2 * Hh;

    // ---- layer 1: agg(x) fused into GEMM (K=128); x -> hw ----
    k_fused<128, false><<<fused_blocks, 256, SMEM_FUSED>>>(
        x, nullptr, nullptr, nullptr, p_whi, p_wlo, p_hw, st0);

    // ---- layer 2: hw -> hw2 (ping-pong: gather reads arbitrary rows) ----
    k_fused<256, true><<<fused_blocks, 256, SMEM_FUSED>>>(
        p_hw, st0, g1, be1, p_whi + 1 * Hh * Hh, p_wlo + 1 * Hh * Hh, p_hw2, st1);

    // ---- layer 3: hw2 -> hw ----
    k_fused<256, true><<<fused_blocks, 256, SMEM_FUSED>>>(
        p_hw2, st1, g2, be2, p_whi + 2 * Hh * Hh, p_wlo + 2 * Hh * Hh, p_hw, st2);

    // ---- head: gather+bn3 from hw; Wl GEMM -> hw2; k_out reads hw2 ----
    k_gather_bn<<<(Tt * 64 + 255) / 256, 256>>>(p_hw, train, st2, g3, be3);
    dim3 head_grid(2, (Tt + 127) / 128);
    k_gemm<<<head_grid, 256, SMEM_GEMM>>>(p_ghi, p_glo, p_whi + 3 * Hh * Hh, p_wlo + 3 * Hh * Hh,
                                          p_hw2, Tt, Hh);
    k_out<<<(Tt * 32 + 255) / 256, 256>>>(p_hw2, bl, Wf, bf, out);
}

// round 11
// speedup vs baseline: 1.2797x; 1.2797x over previous
#include <cuda_runtime.h>
#include <cuda_bf16.h>
#include <mma.h>
#include <cstdint>

using namespace nvcuda;

#define Nn 50000
#define Ee 800000
#define Dd 128
#define Hh 256
#define Tt 10000
#define EPSV 1e-5f
#define SCAN_BLOCKS 196
#define NPAD 50048        // 391 * 128
#define RB_H1 196         // row-blocks in mixed launch
#define ROWS_H1 (RB_H1 * 128)   // 25088

// ---------------- scratch ----------------
__device__ float g_disqrt[Nn];
__device__ int   g_cnt[Nn];
__device__ int   g_off[Nn + 1];
__device__ int   g_cursor[Nn];
__device__ int   g_bsum[SCAN_BLOCKS];
__device__ int   g_csrc[Ee];
__device__ float g_cnorm[Ee];
__device__ float g_hw[(size_t)NPAD * Hh];      // activations ping
__device__ float g_hw2[(size_t)NPAD * Hh];     // activations pong
__device__ float g_stats4[4][2 * Hh];          // per-layer [sum|sumsq]
__device__ __nv_bfloat16 g_ahi[(size_t)Nn * Hh];
__device__ __nv_bfloat16 g_alo[(size_t)Nn * Hh];
__device__ __nv_bfloat16 g_ghi[(size_t)Tt * Hh];
__device__ __nv_bfloat16 g_glo[(size_t)Tt * Hh];
__device__ __nv_bfloat16 g_whi[4 * Hh * Hh];
__device__ __nv_bfloat16 g_wlo[4 * Hh * Hh];

// ---------------- helpers ----------------
__device__ __forceinline__ void cp16(uint32_t dst, const void* src, int bytes) {
    asm volatile("cp.async.cg.shared.global [%0], [%1], 16, %2;"
                 :: "r"(dst), "l"(src), "r"(bytes) : "memory");
}
#define CP_COMMIT() asm volatile("cp.async.commit_group;" ::: "memory")
#define CP_WAIT1()  asm volatile("cp.async.wait_group 1;" ::: "memory")
#define CP_WAIT0()  asm volatile("cp.async.wait_group 0;" ::: "memory")

// ---------------- graph preprocessing ----------------
__global__ void k_zero_init() {
    int i = blockIdx.x * blockDim.x + threadIdx.x;
    if (i < Nn) g_cnt[i] = 0;
    if (i < 4 * 2 * Hh) ((float*)g_stats4)[i] = 0.0f;
}
__global__ void k_count(const int* __restrict__ row) {
    int e = blockIdx.x * blockDim.x + threadIdx.x;
    if (e < Ee) atomicAdd(&g_cnt[row[e]], 1);
}
__global__ void k_scan1() {
    int t = threadIdx.x, b = blockIdx.x;
    int i = b * 256 + t;
    int v = (i < Nn) ? g_cnt[i] : 0;
    if (i < Nn) g_disqrt[i] = rsqrtf((float)v + 1.0f);
    int lane = t & 31, w = t >> 5;
    int x = v;
#pragma unroll
    for (int o = 1; o < 32; o <<= 1) {
        int y = __shfl_up_sync(0xffffffffu, x, o);
        if (lane >= o) x += y;
    }
    __shared__ int wsum[8];
    if (lane == 31) wsum[w] = x;
    __syncthreads();
    if (w == 0) {
        int s = (lane < 8) ? wsum[lane] : 0;
#pragma unroll
        for (int o = 1; o < 8; o <<= 1) {
            int y = __shfl_up_sync(0xffffffffu, s, o);
            if (lane >= o) s += y;
        }
        if (lane < 8) wsum[lane] = s;
    }
    __syncthreads();
    int incl = x + (w > 0 ? wsum[w - 1] : 0);
    if (i < Nn) g_off[i] = incl - v;
    if (t == 255) g_bsum[b] = incl;
}
__global__ void k_scan2() {
    int t = threadIdx.x;
    int v = (t < SCAN_BLOCKS) ? g_bsum[t] : 0;
    int lane = t & 31, w = t >> 5;
    int x = v;
#pragma unroll
    for (int o = 1; o < 32; o <<= 1) {
        int y = __shfl_up_sync(0xffffffffu, x, o);
        if (lane >= o) x += y;
    }
    __shared__ int wsum[8];
    if (lane == 31) wsum[w] = x;
    __syncthreads();
    if (w == 0) {
        int s = (lane < 8) ? wsum[lane] : 0;
#pragma unroll
        for (int o = 1; o < 8; o <<= 1) {
            int y = __shfl_up_sync(0xffffffffu, s, o);
            if (lane >= o) s += y;
        }
        if (lane < 8) wsum[lane] = s;
    }
    __syncthreads();
    int incl = x + (w > 0 ? wsum[w - 1] : 0);
    if (t < SCAN_BLOCKS) g_bsum[t] = incl - v;
}
__global__ void k_scan3() {
    int t = threadIdx.x, b = blockIdx.x;
    int i = b * 256 + t;
    if (i < Nn) {
        int off = g_off[i] + g_bsum[b];
        g_off[i] = off;
        g_cursor[i] = off;
    }
    if (i == 0) g_off[Nn] = Ee;
}
__global__ void k_scatter(const int* __restrict__ row, const int* __restrict__ col) {
    int e = blockIdx.x * blockDim.x + threadIdx.x;
    if (e < Ee) {
        int d = row[e];
        int s = col[e];
        int pos = atomicAdd(&g_cursor[d], 1);
        g_csrc[pos] = s;
        g_cnorm[pos] = g_disqrt[d] * g_disqrt[s];
    }
}

// ---------------- all-weights bf16 split ----------------
__global__ void k_wsplit_all(const float* __restrict__ W1, const float* __restrict__ W2,
                             const float* __restrict__ W3, const float* __restrict__ Wl) {
    int idx = blockIdx.x * blockDim.x + threadIdx.x;
    const int S1 = Dd * Hh;
    const int SW = Hh * Hh;
    const int total = S1 + 3 * SW;
    if (idx >= total) return;
    const float* src;
    int dofs;
    if (idx < S1) { src = W1 + idx; dofs = idx; }
    else {
        int r = idx - S1;
        int which = r / SW, o = r % SW;
        src = (which == 0 ? W2 : which == 1 ? W3 : Wl) + o;
        dofs = (which + 1) * SW + o;
    }
    float v = *src;
    __nv_bfloat16 h = __float2bfloat16_rn(v);
    g_whi[dofs] = h;
    g_wlo[dofs] = __float2bfloat16_rn(v - __bfloat162float(h));
}

// ---------------- aggregation body (R8: warp per node, full-row float4) ----------------
template <int KC, bool BN>
__device__ __forceinline__ void agg_body(int node, const float* __restrict__ src,
                                         const float* __restrict__ stats_in,
                                         const float* __restrict__ gamma,
                                         const float* __restrict__ beta,
                                         __nv_bfloat16* __restrict__ dhi,
                                         __nv_bfloat16* __restrict__ dlo, int lane) {
    constexpr int Q = KC / 128;
    float scale[Q][4], shift[Q][4];
    if (BN) {
        const float invN = 1.0f / (float)Nn;
#pragma unroll
        for (int q = 0; q < Q; q++)
#pragma unroll
            for (int k = 0; k < 4; k++) {
                int j = q * 128 + lane * 4 + k;
                float mu = stats_in[j] * invN;
                float var = fmaxf(stats_in[Hh + j] * invN - mu * mu, 0.0f);
                float sc = gamma[j] * rsqrtf(var + EPSV);
                scale[q][k] = sc;
                shift[q][k] = beta[j] - mu * sc;
            }
    }

    const float4* s4 = (const float4*)src;
    float dsq = g_disqrt[node];
    float sl = dsq * dsq;

    float acc[Q][4];
#pragma unroll
    for (int q = 0; q < Q; q++) {
        float4 v = s4[(size_t)node * (Q * 32) + q * 32 + lane];
        float t[4] = {v.x, v.y, v.z, v.w};
#pragma unroll
        for (int k = 0; k < 4; k++) {
            float u = BN ? fmaxf(fmaf(t[k], scale[q][k], shift[q][k]), 0.0f) : t[k];
            acc[q][k] = u * sl;
        }
    }
    int e0 = g_off[node], e1 = g_off[node + 1];
    for (int e = e0; e < e1; e++) {
        int s = g_csrc[e];
        float nm = g_cnorm[e];
#pragma unroll
        for (int q = 0; q < Q; q++) {
            float4 v = s4[(size_t)s * (Q * 32) + q * 32 + lane];
            float t[4] = {v.x, v.y, v.z, v.w};
#pragma unroll
            for (int k = 0; k < 4; k++) {
                float u = BN ? fmaxf(fmaf(t[k], scale[q][k], shift[q][k]), 0.0f) : t[k];
                acc[q][k] = fmaf(u, nm, acc[q][k]);
            }
        }
    }
#pragma unroll
    for (int q = 0; q < Q; q++) {
        size_t base = (size_t)node * KC + q * 128 + lane * 4;
        float h[4], l[4];
#pragma unroll
        for (int k = 0; k < 4; k++) {
            __nv_bfloat16 hb = __float2bfloat16_rn(acc[q][k]);
            h[k] = __bfloat162float(hb);
            l[k] = acc[q][k] - h[k];
        }
        *(__nv_bfloat162*)(dhi + base) = __floats2bfloat162_rn(h[0], h[1]);
        *(__nv_bfloat162*)(dhi + base + 2) = __floats2bfloat162_rn(h[2], h[3]);
        *(__nv_bfloat162*)(dlo + base) = __floats2bfloat162_rn(l[0], l[1]);
        *(__nv_bfloat162*)(dlo + base + 2) = __floats2bfloat162_rn(l[2], l[3]);
    }
}

template <int KC, bool BN>
__global__ void k_agg_t(int base, int count, const float* __restrict__ src,
                        const float* __restrict__ stats_in,
                        const float* __restrict__ gamma, const float* __restrict__ beta,
                        __nv_bfloat16* __restrict__ dhi, __nv_bfloat16* __restrict__ dlo) {
    int wid = threadIdx.x >> 5, lane = threadIdx.x & 31;
    int node = base + blockIdx.x * 8 + wid;
    if (node < base + count && node < Nn)
        agg_body<KC, BN>(node, src, stats_in, gamma, beta, dhi, dlo, lane);
}

// ---------------- GEMM body (R8: 3xBF16 wmma, cp.async, fused stats) ----------------
#define GBK 32
#define ALD 40
#define BLD 136
#define CLD 132
#define STAGE_BYTES ((2 * 128 * ALD * 2 + 2 * GBK * BLD * 2) * 2)  // 75776
#define CTILE_BYTES (128 * CLD * 4)                                 // 67584
#define SMEM_GEMM (STAGE_BYTES > CTILE_BYTES ? STAGE_BYTES : CTILE_BYTES)

using AFrag = wmma::fragment<wmma::matrix_a, 16, 16, 16, __nv_bfloat16, wmma::row_major>;
using BFrag = wmma::fragment<wmma::matrix_b, 16, 16, 16, __nv_bfloat16, wmma::row_major>;
using CFrag = wmma::fragment<wmma::accumulator, 16, 16, 16, float>;

__device__ __forceinline__ void gemm_body(const __nv_bfloat16* __restrict__ Ahi,
                                          const __nv_bfloat16* __restrict__ Alo,
                                          const __nv_bfloat16* __restrict__ Bhi,
                                          const __nv_bfloat16* __restrict__ Blo,
                                          float* __restrict__ C, float* __restrict__ stats,
                                          int M, int K, int rowBase, int colBase,
                                          __nv_bfloat16* sm) {
    __nv_bfloat16* AH = sm;
    __nv_bfloat16* AL = AH + 2 * 128 * ALD;
    __nv_bfloat16* BH = AL + 2 * 128 * ALD;
    __nv_bfloat16* BL = BH + 2 * GBK * BLD;

    const int tid = threadIdx.x;
    const int warp = tid >> 5;
    const int wm = warp & 3;
    const int wn = warp >> 2;

    CFrag c[2][4];
#pragma unroll
    for (int i = 0; i < 2; i++)
#pragma unroll
        for (int j = 0; j < 4; j++) wmma::fill_fragment(c[i][j], 0.0f);

    auto load_stage = [&](int buf, int k0) {
#pragma unroll
        for (int t = 0; t < 2; t++) {
            int id = tid + t * 256;
            int r = id >> 2;
            int cc = (id & 3) * 8;
            int grow = rowBase + r;
            size_t gofs = (size_t)(grow < M ? grow : 0) * K + k0 + cc;
            int bytes = grow < M ? 16 : 0;
            cp16((uint32_t)__cvta_generic_to_shared(AH + ((size_t)buf * 128 + r) * ALD + cc),
                 Ahi + gofs, bytes);
            cp16((uint32_t)__cvta_generic_to_shared(AL + ((size_t)buf * 128 + r) * ALD + cc),
                 Alo + gofs, bytes);
        }
#pragma unroll
        for (int t = 0; t < 2; t++) {
            int id = tid + t * 256;
            int kr = id >> 4;
            int nc = (id & 15) * 8;
            size_t gofs = (size_t)(k0 + kr) * Hh + colBase + nc;
            cp16((uint32_t)__cvta_generic_to_shared(BH + ((size_t)buf * GBK + kr) * BLD + nc),
                 Bhi + gofs, 16);
            cp16((uint32_t)__cvta_generic_to_shared(BL + ((size_t)buf * GBK + kr) * BLD + nc),
                 Blo + gofs, 16);
        }
    };

    const int NC = K >> 5;
    load_stage(0, 0);
    CP_COMMIT();

    for (int cidx = 0; cidx < NC; cidx++) {
        int buf = cidx & 1;
        if (cidx + 1 < NC) {
            load_stage(buf ^ 1, (cidx + 1) << 5);
            CP_COMMIT();
            CP_WAIT1();
        } else {
            CP_WAIT0();
        }
        __syncthreads();

#pragma unroll
        for (int ks = 0; ks < 2; ks++) {
            AFrag ah[2], al[2];
            BFrag bh[4], bl[4];
#pragma unroll
            for (int i = 0; i < 2; i++) {
                const __nv_bfloat16* pa = AH + ((size_t)buf * 128 + wm * 32 + i * 16) * ALD + ks * 16;
                wmma::load_matrix_sync(ah[i], pa, ALD);
                wmma::load_matrix_sync(al[i], pa + 2 * 128 * ALD, ALD);
            }
#pragma unroll
            for (int j = 0; j < 4; j++) {
                const __nv_bfloat16* pb = BH + ((size_t)buf * GBK + ks * 16) * BLD + wn * 64 + j * 16;
                wmma::load_matrix_sync(bh[j], pb, BLD);
                wmma::load_matrix_sync(bl[j], pb + 2 * GBK * BLD, BLD);
            }
#pragma unroll
            for (int i = 0; i < 2; i++)
#pragma unroll
                for (int j = 0; j < 4; j++) {
                    wmma::mma_sync(c[i][j], ah[i], bh[j], c[i][j]);
                    wmma::mma_sync(c[i][j], ah[i], bl[j], c[i][j]);
                    wmma::mma_sync(c[i][j], al[i], bh[j], c[i][j]);
                }
        }
        __syncthreads();
    }

#pragma unroll
    for (int i = 0; i < 2; i++)
#pragma unroll
        for (int j = 0; j < 4; j++) {
            int grow = rowBase + wm * 32 + i * 16;
            wmma::store_matrix_sync(C + (size_t)grow * Hh + colBase + wn * 64 + j * 16,
                                    c[i][j], Hh, wmma::mem_row_major);
        }

    if (stats) {
        float* ct = (float*)sm;
#pragma unroll
        for (int i = 0; i < 2; i++)
#pragma unroll
            for (int j = 0; j < 4; j++)
                wmma::store_matrix_sync(ct + (size_t)(wm * 32 + i * 16) * CLD + wn * 64 + j * 16,
                                        c[i][j], CLD, wmma::mem_row_major);
        __syncthreads();
        int col = tid & 127;
        int half = tid >> 7;
        const float* p = ct + (size_t)half * 64 * CLD + col;
        float s = 0.f, s2 = 0.f;
#pragma unroll 8
        for (int r = 0; r < 64; r++) {
            float v = p[(size_t)r * CLD];
            s += v;
            s2 = fmaf(v, v, s2);
        }
        atomicAdd(&stats[colBase + col], s);
        atomicAdd(&stats[Hh + colBase + col], s2);
    }
}

// standalone GEMM (tail rows + head)
__global__ __launch_bounds__(256) void k_gemm_std(const __nv_bfloat16* __restrict__ Ahi,
                                                  const __nv_bfloat16* __restrict__ Alo,
                                                  const __nv_bfloat16* __restrict__ Bhi,
                                                  const __nv_bfloat16* __restrict__ Blo,
                                                  float* __restrict__ C,
                                                  float* __restrict__ stats,
                                                  int M, int K, int rb0) {
    extern __shared__ __nv_bfloat16 sm[];
    gemm_body(Ahi, Alo, Bhi, Blo, C, stats, M, K, (rb0 + blockIdx.y) * 128,
              blockIdx.x * 128, sm);
}

// mixed launch: gemm blocks on H1 rows + agg blocks on H2 nodes (co-resident overlap)
template <int KC, bool BN>
__global__ __launch_bounds__(256, 2) void k_mix(
    int ngemm, int agg_base,
    const float* __restrict__ src, const float* __restrict__ stats_in,
    const float* __restrict__ gamma, const float* __restrict__ beta,
    __nv_bfloat16* __restrict__ ahi, __nv_bfloat16* __restrict__ alo,
    const __nv_bfloat16* __restrict__ whi, const __nv_bfloat16* __restrict__ wlo,
    float* __restrict__ C, float* __restrict__ stats_out) {
    extern __shared__ __nv_bfloat16 sm[];
    if (blockIdx.x < (unsigned)ngemm) {
        int rb = blockIdx.x >> 1, cb = blockIdx.x & 1;
        gemm_body(ahi, alo, whi, wlo, C, stats_out, Nn, KC, rb * 128, cb * 128, sm);
    } else {
        int wid = threadIdx.x >> 5, lane = threadIdx.x & 31;
        int node = agg_base + (blockIdx.x - ngemm) * 8 + wid;
        if (node < Nn)
            agg_body<KC, BN>(node, src, stats_in, gamma, beta, ahi, alo, lane);
    }
}

// ---------------- head: gather + BN3 + relu + bf16 split ----------------
__global__ void k_gather_bn(const float* __restrict__ hsrc,
                            const int* __restrict__ train, const float* __restrict__ stats,
                            const float* __restrict__ gamma, const float* __restrict__ beta) {
    int idx = blockIdx.x * blockDim.x + threadIdx.x;
    if (idx >= Tt * 64) return;
    int t = idx >> 6, cq = idx & 63;
    int node = train[t];
    float4 v = ((const float4*)hsrc)[(size_t)node * 64 + cq];
    const float invN = 1.0f / (float)Nn;
    float tv[4] = {v.x, v.y, v.z, v.w};
    float h[4], l[4];
#pragma unroll
    for (int k = 0; k < 4; k++) {
        int j = cq * 4 + k;
        float mu = stats[j] * invN;
        float var = fmaxf(stats[Hh + j] * invN - mu * mu, 0.0f);
        float sc = gamma[j] * rsqrtf(var + EPSV);
        float u = fmaxf(fmaf(tv[k], sc, beta[j] - mu * sc), 0.0f);
        __nv_bfloat16 hb = __float2bfloat16_rn(u);
        h[k] = __bfloat162float(hb);
        l[k] = u - h[k];
    }
    size_t base = (size_t)t * Hh + cq * 4;
    *(__nv_bfloat162*)(g_ghi + base) = __floats2bfloat162_rn(h[0], h[1]);
    *(__nv_bfloat162*)(g_ghi + base + 2) = __floats2bfloat162_rn(h[2], h[3]);
    *(__nv_bfloat162*)(g_glo + base) = __floats2bfloat162_rn(l[0], l[1]);
    *(__nv_bfloat162*)(g_glo + base + 2) = __floats2bfloat162_rn(l[2], l[3]);
}

__global__ void k_out(const float* __restrict__ hsrc,
                      const float* __restrict__ bl, const float* __restrict__ Wf,
                      const float* __restrict__ bf, float* __restrict__ out) {
    int warp = (blockIdx.x * blockDim.x + threadIdx.x) >> 5;
    int lane = threadIdx.x & 31;
    if (warp >= Tt) return;
    float acc = 0.f;
    const float* hp = hsrc + (size_t)warp * Hh;
#pragma unroll
    for (int j0 = 0; j0 < Hh; j0 += 32) {
        int j = j0 + lane;
        float v = fmaxf(hp[j] + bl[j], 0.0f);
        acc = fmaf(v, Wf[j], acc);
    }
#pragma unroll
    for (int o = 16; o > 0; o >>= 1) acc += __shfl_xor_sync(0xffffffffu, acc, o);
    if (lane == 0) out[warp] = acc + bf[0];
}

// ---------------- launch ----------------
extern "C" void kernel_launch(void* const* d_in, const int* in_sizes, int n_in,
                              void* d_out, int out_size) {
    const float* x = (const float*)d_in[0];
    const int* ei = (const int*)d_in[1];
    const int* train = (const int*)d_in[2];
    const float* W1 = (const float*)d_in[3];
    const float* W2 = (const float*)d_in[5];
    const float* W3 = (const float*)d_in[7];
    const float* g1 = (const float*)d_in[9];
    const float* be1 = (const float*)d_in[10];
    const float* g2 = (const float*)d_in[11];
    const float* be2 = (const float*)d_in[12];
    const float* g3 = (const float*)d_in[13];
    const float* be3 = (const float*)d_in[14];
    const float* Wl = (const float*)d_in[15];
    const float* bl = (const float*)d_in[16];
    const float* Wf = (const float*)d_in[17];
    const float* bf = (const float*)d_in[18];
    float* out = (float*)d_out;

    const int* row = ei;
    const int* col = ei + Ee;

    float *p_hw, *p_hw2, *p_stats;
    __nv_bfloat16 *p_ahi, *p_alo, *p_ghi, *p_glo, *p_whi, *p_wlo;
    cudaGetSymbolAddress((void**)&p_hw, g_hw);
    cudaGetSymbolAddress((void**)&p_hw2, g_hw2);
    cudaGetSymbolAddress((void**)&p_stats, g_stats4);
    cudaGetSymbolAddress((void**)&p_ahi, g_ahi);
    cudaGetSymbolAddress((void**)&p_alo, g_alo);
    cudaGetSymbolAddress((void**)&p_ghi, g_ghi);
    cudaGetSymbolAddress((void**)&p_glo, g_glo);
    cudaGetSymbolAddress((void**)&p_whi, g_whi);
    cudaGetSymbolAddress((void**)&p_wlo, g_wlo);

    cudaFuncSetAttribute(k_gemm_std, cudaFuncAttributeMaxDynamicSharedMemorySize, SMEM_GEMM);
    cudaFuncSetAttribute(k_mix<128, false>, cudaFuncAttributeMaxDynamicSharedMemorySize, SMEM_GEMM);
    cudaFuncSetAttribute(k_mix<256, true>, cudaFuncAttributeMaxDynamicSharedMemorySize, SMEM_GEMM);

    // ---- graph preprocessing ----
    k_zero_init<<<(Nn + 255) / 256, 256>>>();
    k_count<<<(Ee + 255) / 256, 256>>>(row);
    k_scan1<<<SCAN_BLOCKS, 256>>>();
    k_scan2<<<1, 256>>>();
    k_scan3<<<SCAN_BLOCKS, 256>>>();
    k_scatter<<<(Ee + 255) / 256, 256>>>(row, col);
    k_wsplit_all<<<(Dd * Hh + 3 * Hh * Hh + 255) / 256, 256>>>(W1, W2, W3, Wl);

    const int NGEMM = RB_H1 * 2;                       // 392
    const int AGG1_BLOCKS = ROWS_H1 / 8;               // 3136
    const int AGG2_NODES = Nn - ROWS_H1;               // 24912
    const int AGG2_BLOCKS = (AGG2_NODES + 7) / 8;      // 3114
    dim3 tail_grid(2, NPAD / 128 - RB_H1);             // (2,195)
    float* st0 = p_stats + 0 * 2 * Hh;
    float* st1 = p_stats + 1 * 2 * Hh;
    float* st2 = p_stats + 2 * 2 * Hh;

    // ---- layer 1: src=x -> hw (K=128) ----
    k_agg_t<128, false><<<AGG1_BLOCKS, 256>>>(0, ROWS_H1, x, nullptr, nullptr, nullptr,
                                              p_ahi, p_alo);
    k_mix<128, false><<<NGEMM + AGG2_BLOCKS, 256, SMEM_GEMM>>>(
        NGEMM, ROWS_H1, x, nullptr, nullptr, nullptr, p_ahi, p_alo,
        p_whi, p_wlo, p_hw, st0);
    k_gemm_std<<<tail_grid, 256, SMEM_GEMM>>>(p_ahi, p_alo, p_whi, p_wlo,
                                              p_hw, st0, Nn, Dd, RB_H1);

    // ---- layer 2: hw -> hw2 ----
    k_agg_t<256, true><<<AGG1_BLOCKS, 256>>>(0, ROWS_H1, p_hw, st0, g1, be1, p_ahi, p_alo);
    k_mix<256, true><<<NGEMM + AGG2_BLOCKS, 256, SMEM_GEMM>>>(
        NGEMM, ROWS_H1, p_hw, st0, g1, be1, p_ahi, p_alo,
        p_whi + 1 * Hh * Hh, p_wlo + 1 * Hh * Hh, p_hw2, st1);
    k_gemm_std<<<tail_grid, 256, SMEM_GEMM>>>(p_ahi, p_alo, p_whi + 1 * Hh * Hh,
                                              p_wlo + 1 * Hh * Hh, p_hw2, st1, Nn, Hh, RB_H1);

    // ---- layer 3: hw2 -> hw ----
    k_agg_t<256, true><<<AGG1_BLOCKS, 256>>>(0, ROWS_H1, p_hw2, st1, g2, be2, p_ahi, p_alo);
    k_mix<256, true><<<NGEMM + AGG2_BLOCKS, 256, SMEM_GEMM>>>(
        NGEMM, ROWS_H1, p_hw2, st1, g2, be2, p_ahi, p_alo,
        p_whi + 2 * Hh * Hh, p_wlo + 2 * Hh * Hh, p_hw, st2);
    k_gemm_std<<<tail_grid, 256, SMEM_GEMM>>>(p_ahi, p_alo, p_whi + 2 * Hh * Hh,
                                              p_wlo + 2 * Hh * Hh, p_hw, st2, Nn, Hh, RB_H1);

    // ---- head: gather+bn3 from hw; Wl GEMM -> hw2; k_out ----
    k_gather_bn<<<(Tt * 64 + 255) / 256, 256>>>(p_hw, train, st2, g3, be3);
    dim3 head_grid(2, (Tt + 127) / 128);
    k_gemm_std<<<head_grid, 256, SMEM_GEMM>>>(p_ghi, p_glo, p_whi + 3 * Hh * Hh,
                                              p_wlo + 3 * Hh * Hh, p_hw2, nullptr, Tt, Hh, 0);
    k_out<<<(Tt * 32 + 255) / 256, 256>>>(p_hw2, bl, Wf, bf, out);
}

// round 12
// speedup vs baseline: 1.3365x; 1.0444x over previous
#include <cuda_runtime.h>
#include <cuda_bf16.h>
#include <mma.h>
#include <cstdint>

using namespace nvcuda;

#define Nn 50000
#define Ee 800000
#define Dd 128
#define Hh 256
#define Tt 10000
#define EPSV 1e-5f
#define SCAN_BLOCKS 196
#define NPAD 50048        // 391 * 128
#define RB_ALL (NPAD / 128)     // 391
#define RB_H1 196
#define ROWS_H1 (RB_H1 * 128)   // 25088

// ---------------- scratch ----------------
__device__ float g_disqrt[Nn];
__device__ int   g_cnt[Nn];
__device__ int   g_off[Nn + 1];
__device__ int   g_cursor[Nn];
__device__ int   g_bsum[SCAN_BLOCKS];
__device__ int   g_csrc[Ee];
__device__ float g_cnorm[Ee];
__device__ float g_hw[(size_t)NPAD * Hh];      // activations ping
__device__ float g_hw2[(size_t)NPAD * Hh];     // activations pong
__device__ float g_stats4[4][2 * Hh];
__device__ __nv_bfloat16 g_ahi[(size_t)Nn * Hh];
__device__ __nv_bfloat16 g_alo[(size_t)Nn * Hh];
__device__ __nv_bfloat16 g_ghi[(size_t)Tt * Hh];
__device__ __nv_bfloat16 g_glo[(size_t)Tt * Hh];
__device__ __nv_bfloat16 g_whi[4 * Hh * Hh];
__device__ __nv_bfloat16 g_wlo[4 * Hh * Hh];

// ---------------- helpers ----------------
__device__ __forceinline__ void cp16(uint32_t dst, const void* src, int bytes) {
    asm volatile("cp.async.cg.shared.global [%0], [%1], 16, %2;"
                 :: "r"(dst), "l"(src), "r"(bytes) : "memory");
}
#define CP_COMMIT() asm volatile("cp.async.commit_group;" ::: "memory")
#define CP_WAIT1()  asm volatile("cp.async.wait_group 1;" ::: "memory")
#define CP_WAIT0()  asm volatile("cp.async.wait_group 0;" ::: "memory")

// ---------------- graph preprocessing ----------------
__global__ void k_zero_init() {
    int i = blockIdx.x * blockDim.x + threadIdx.x;
    if (i < Nn) g_cnt[i] = 0;
    if (i < 4 * 2 * Hh) ((float*)g_stats4)[i] = 0.0f;
}
__global__ void k_count(const int* __restrict__ row) {
    int e = blockIdx.x * blockDim.x + threadIdx.x;
    if (e < Ee) atomicAdd(&g_cnt[row[e]], 1);
}
__global__ void k_scan1() {
    int t = threadIdx.x, b = blockIdx.x;
    int i = b * 256 + t;
    int v = (i < Nn) ? g_cnt[i] : 0;
    if (i < Nn) g_disqrt[i] = rsqrtf((float)v + 1.0f);
    int lane = t & 31, w = t >> 5;
    int x = v;
#pragma unroll
    for (int o = 1; o < 32; o <<= 1) {
        int y = __shfl_up_sync(0xffffffffu, x, o);
        if (lane >= o) x += y;
    }
    __shared__ int wsum[8];
    if (lane == 31) wsum[w] = x;
    __syncthreads();
    if (w == 0) {
        int s = (lane < 8) ? wsum[lane] : 0;
#pragma unroll
        for (int o = 1; o < 8; o <<= 1) {
            int y = __shfl_up_sync(0xffffffffu, s, o);
            if (lane >= o) s += y;
        }
        if (lane < 8) wsum[lane] = s;
    }
    __syncthreads();
    int incl = x + (w > 0 ? wsum[w - 1] : 0);
    if (i < Nn) g_off[i] = incl - v;
    if (t == 255) g_bsum[b] = incl;
}
__global__ void k_scan2() {
    int t = threadIdx.x;
    int v = (t < SCAN_BLOCKS) ? g_bsum[t] : 0;
    int lane = t & 31, w = t >> 5;
    int x = v;
#pragma unroll
    for (int o = 1; o < 32; o <<= 1) {
        int y = __shfl_up_sync(0xffffffffu, x, o);
        if (lane >= o) x += y;
    }
    __shared__ int wsum[8];
    if (lane == 31) wsum[w] = x;
    __syncthreads();
    if (w == 0) {
        int s = (lane < 8) ? wsum[lane] : 0;
#pragma unroll
        for (int o = 1; o < 8; o <<= 1) {
            int y = __shfl_up_sync(0xffffffffu, s, o);
            if (lane >= o) s += y;
        }
        if (lane < 8) wsum[lane] = s;
    }
    __syncthreads();
    int incl = x + (w > 0 ? wsum[w - 1] : 0);
    if (t < SCAN_BLOCKS) g_bsum[t] = incl - v;
}
__global__ void k_scan3() {
    int t = threadIdx.x, b = blockIdx.x;
    int i = b * 256 + t;
    if (i < Nn) {
        int off = g_off[i] + g_bsum[b];
        g_off[i] = off;
        g_cursor[i] = off;
    }
    if (i == 0) g_off[Nn] = Ee;
}
__global__ void k_scatter(const int* __restrict__ row, const int* __restrict__ col) {
    int e = blockIdx.x * blockDim.x + threadIdx.x;
    if (e < Ee) {
        int d = row[e];
        int s = col[e];
        int pos = atomicAdd(&g_cursor[d], 1);
        g_csrc[pos] = s;
        g_cnorm[pos] = g_disqrt[d] * g_disqrt[s];
    }
}

// ---------------- all-weights bf16 split ----------------
__global__ void k_wsplit_all(const float* __restrict__ W1, const float* __restrict__ W2,
                             const float* __restrict__ W3, const float* __restrict__ Wl) {
    int idx = blockIdx.x * blockDim.x + threadIdx.x;
    const int S1 = Dd * Hh;
    const int SW = Hh * Hh;
    const int total = S1 + 3 * SW;
    if (idx >= total) return;
    const float* src;
    int dofs;
    if (idx < S1) { src = W1 + idx; dofs = idx; }
    else {
        int r = idx - S1;
        int which = r / SW, o = r % SW;
        src = (which == 0 ? W2 : which == 1 ? W3 : Wl) + o;
        dofs = (which + 1) * SW + o;
    }
    float v = *src;
    __nv_bfloat16 h = __float2bfloat16_rn(v);
    g_whi[dofs] = h;
    g_wlo[dofs] = __float2bfloat16_rn(v - __bfloat162float(h));
}

// ---------------- aggregation (warp per node, full-row float4) ----------------
template <int KC, bool BN>
__global__ void k_agg(int base, int count, const float* __restrict__ src,
                      const float* __restrict__ stats_in,
                      const float* __restrict__ gamma, const float* __restrict__ beta,
                      __nv_bfloat16* __restrict__ dhi, __nv_bfloat16* __restrict__ dlo) {
    constexpr int Q = KC / 128;
    int wid = threadIdx.x >> 5, lane = threadIdx.x & 31;
    int node = base + blockIdx.x * 8 + wid;
    if (node >= base + count || node >= Nn) return;

    float scale[Q][4], shift[Q][4];
    if (BN) {
        const float invN = 1.0f / (float)Nn;
#pragma unroll
        for (int q = 0; q < Q; q++)
#pragma unroll
            for (int k = 0; k < 4; k++) {
                int j = q * 128 + lane * 4 + k;
                float mu = stats_in[j] * invN;
                float var = fmaxf(stats_in[Hh + j] * invN - mu * mu, 0.0f);
                float sc = gamma[j] * rsqrtf(var + EPSV);
                scale[q][k] = sc;
                shift[q][k] = beta[j] - mu * sc;
            }
    }

    const float4* s4 = (const float4*)src;
    float dsq = g_disqrt[node];
    float sl = dsq * dsq;

    float acc[Q][4];
#pragma unroll
    for (int q = 0; q < Q; q++) {
        float4 v = s4[(size_t)node * (Q * 32) + q * 32 + lane];
        float t[4] = {v.x, v.y, v.z, v.w};
#pragma unroll
        for (int k = 0; k < 4; k++) {
            float u = BN ? fmaxf(fmaf(t[k], scale[q][k], shift[q][k]), 0.0f) : t[k];
            acc[q][k] = u * sl;
        }
    }
    int e0 = g_off[node], e1 = g_off[node + 1];
    for (int e = e0; e < e1; e++) {
        int s = g_csrc[e];
        float nm = g_cnorm[e];
#pragma unroll
        for (int q = 0; q < Q; q++) {
            float4 v = s4[(size_t)s * (Q * 32) + q * 32 + lane];
            float t[4] = {v.x, v.y, v.z, v.w};
#pragma unroll
            for (int k = 0; k < 4; k++) {
                float u = BN ? fmaxf(fmaf(t[k], scale[q][k], shift[q][k]), 0.0f) : t[k];
                acc[q][k] = fmaf(u, nm, acc[q][k]);
            }
        }
    }
#pragma unroll
    for (int q = 0; q < Q; q++) {
        size_t bb = (size_t)node * KC + q * 128 + lane * 4;
        float h[4], l[4];
#pragma unroll
        for (int k = 0; k < 4; k++) {
            __nv_bfloat16 hb = __float2bfloat16_rn(acc[q][k]);
            h[k] = __bfloat162float(hb);
            l[k] = acc[q][k] - h[k];
        }
        *(__nv_bfloat162*)(dhi + bb) = __floats2bfloat162_rn(h[0], h[1]);
        *(__nv_bfloat162*)(dhi + bb + 2) = __floats2bfloat162_rn(h[2], h[3]);
        *(__nv_bfloat162*)(dlo + bb) = __floats2bfloat162_rn(l[0], l[1]);
        *(__nv_bfloat162*)(dlo + bb + 2) = __floats2bfloat162_rn(l[2], l[3]);
    }
}

// ---------------- 3xBF16 wmma GEMM, cp.async, fused stats ----------------
#define GBK 32
#define ALD 40
#define BLD 136
#define CLD 132
#define STAGE_BYTES ((2 * 128 * ALD * 2 + 2 * GBK * BLD * 2) * 2)  // 75776
#define CTILE_BYTES (128 * CLD * 4)                                 // 67584
#define SMEM_GEMM (STAGE_BYTES > CTILE_BYTES ? STAGE_BYTES : CTILE_BYTES)

using AFrag = wmma::fragment<wmma::matrix_a, 16, 16, 16, __nv_bfloat16, wmma::row_major>;
using BFrag = wmma::fragment<wmma::matrix_b, 16, 16, 16, __nv_bfloat16, wmma::row_major>;
using CFrag = wmma::fragment<wmma::accumulator, 16, 16, 16, float>;

__global__ __launch_bounds__(256) void k_gemm(const __nv_bfloat16* __restrict__ Ahi,
                                              const __nv_bfloat16* __restrict__ Alo,
                                              const __nv_bfloat16* __restrict__ Bhi,
                                              const __nv_bfloat16* __restrict__ Blo,
                                              float* __restrict__ C,
                                              float* __restrict__ stats,
                                              int M, int K, int rb0) {
    extern __shared__ __nv_bfloat16 sm[];
    __nv_bfloat16* AH = sm;
    __nv_bfloat16* AL = AH + 2 * 128 * ALD;
    __nv_bfloat16* BH = AL + 2 * 128 * ALD;
    __nv_bfloat16* BL = BH + 2 * GBK * BLD;

    const int tid = threadIdx.x;
    const int warp = tid >> 5;
    const int rowBase = (rb0 + blockIdx.y) * 128;
    const int colBase = blockIdx.x * 128;
    const int wm = warp & 3;
    const int wn = warp >> 2;

    CFrag c[2][4];
#pragma unroll
    for (int i = 0; i < 2; i++)
#pragma unroll
        for (int j = 0; j < 4; j++) wmma::fill_fragment(c[i][j], 0.0f);

    auto load_stage = [&](int buf, int k0) {
#pragma unroll
        for (int t = 0; t < 2; t++) {
            int id = tid + t * 256;
            int r = id >> 2;
            int cc = (id & 3) * 8;
            int grow = rowBase + r;
            size_t gofs = (size_t)(grow < M ? grow : 0) * K + k0 + cc;
            int bytes = grow < M ? 16 : 0;
            cp16((uint32_t)__cvta_generic_to_shared(AH + ((size_t)buf * 128 + r) * ALD + cc),
                 Ahi + gofs, bytes);
            cp16((uint32_t)__cvta_generic_to_shared(AL + ((size_t)buf * 128 + r) * ALD + cc),
                 Alo + gofs, bytes);
        }
#pragma unroll
        for (int t = 0; t < 2; t++) {
            int id = tid + t * 256;
            int kr = id >> 4;
            int nc = (id & 15) * 8;
            size_t gofs = (size_t)(k0 + kr) * Hh + colBase + nc;
            cp16((uint32_t)__cvta_generic_to_shared(BH + ((size_t)buf * GBK + kr) * BLD + nc),
                 Bhi + gofs, 16);
            cp16((uint32_t)__cvta_generic_to_shared(BL + ((size_t)buf * GBK + kr) * BLD + nc),
                 Blo + gofs, 16);
        }
    };

    const int NC = K >> 5;
    load_stage(0, 0);
    CP_COMMIT();

    for (int cidx = 0; cidx < NC; cidx++) {
        int buf = cidx & 1;
        if (cidx + 1 < NC) {
            load_stage(buf ^ 1, (cidx + 1) << 5);
            CP_COMMIT();
            CP_WAIT1();
        } else {
            CP_WAIT0();
        }
        __syncthreads();

#pragma unroll
        for (int ks = 0; ks < 2; ks++) {
            AFrag ah[2], al[2];
            BFrag bh[4], bl[4];
#pragma unroll
            for (int i = 0; i < 2; i++) {
                const __nv_bfloat16* pa = AH + ((size_t)buf * 128 + wm * 32 + i * 16) * ALD + ks * 16;
                wmma::load_matrix_sync(ah[i], pa, ALD);
                wmma::load_matrix_sync(al[i], pa + 2 * 128 * ALD, ALD);
            }
#pragma unroll
            for (int j = 0; j < 4; j++) {
                const __nv_bfloat16* pb = BH + ((size_t)buf * GBK + ks * 16) * BLD + wn * 64 + j * 16;
                wmma::load_matrix_sync(bh[j], pb, BLD);
                wmma::load_matrix_sync(bl[j], pb + 2 * GBK * BLD, BLD);
            }
#pragma unroll
            for (int i = 0; i < 2; i++)
#pragma unroll
                for (int j = 0; j < 4; j++) {
                    wmma::mma_sync(c[i][j], ah[i], bh[j], c[i][j]);
                    wmma::mma_sync(c[i][j], ah[i], bl[j], c[i][j]);
                    wmma::mma_sync(c[i][j], al[i], bh[j], c[i][j]);
                }
        }
        __syncthreads();
    }

#pragma unroll
    for (int i = 0; i < 2; i++)
#pragma unroll
        for (int j = 0; j < 4; j++) {
            int grow = rowBase + wm * 32 + i * 16;
            wmma::store_matrix_sync(C + (size_t)grow * Hh + colBase + wn * 64 + j * 16,
                                    c[i][j], Hh, wmma::mem_row_major);
        }

    if (stats) {
        float* ct = (float*)sm;
#pragma unroll
        for (int i = 0; i < 2; i++)
#pragma unroll
            for (int j = 0; j < 4; j++)
                wmma::store_matrix_sync(ct + (size_t)(wm * 32 + i * 16) * CLD + wn * 64 + j * 16,
                                        c[i][j], CLD, wmma::mem_row_major);
        __syncthreads();
        int col = tid & 127;
        int half = tid >> 7;
        const float* p = ct + (size_t)half * 64 * CLD + col;
        float s = 0.f, s2 = 0.f;
#pragma unroll 8
        for (int r = 0; r < 64; r++) {
            float v = p[(size_t)r * CLD];
            s += v;
            s2 = fmaf(v, v, s2);
        }
        atomicAdd(&stats[colBase + col], s);
        atomicAdd(&stats[Hh + colBase + col], s2);
    }
}

// ---------------- head: gather + BN3 + relu + bf16 split ----------------
__global__ void k_gather_bn(const float* __restrict__ hsrc,
                            const int* __restrict__ train, const float* __restrict__ stats,
                            const float* __restrict__ gamma, const float* __restrict__ beta) {
    int idx = blockIdx.x * blockDim.x + threadIdx.x;
    if (idx >= Tt * 64) return;
    int t = idx >> 6, cq = idx & 63;
    int node = train[t];
    float4 v = ((const float4*)hsrc)[(size_t)node * 64 + cq];
    const float invN = 1.0f / (float)Nn;
    float tv[4] = {v.x, v.y, v.z, v.w};
    float h[4], l[4];
#pragma unroll
    for (int k = 0; k < 4; k++) {
        int j = cq * 4 + k;
        float mu = stats[j] * invN;
        float var = fmaxf(stats[Hh + j] * invN - mu * mu, 0.0f);
        float sc = gamma[j] * rsqrtf(var + EPSV);
        float u = fmaxf(fmaf(tv[k], sc, beta[j] - mu * sc), 0.0f);
        __nv_bfloat16 hb = __float2bfloat16_rn(u);
        h[k] = __bfloat162float(hb);
        l[k] = u - h[k];
    }
    size_t base = (size_t)t * Hh + cq * 4;
    *(__nv_bfloat162*)(g_ghi + base) = __floats2bfloat162_rn(h[0], h[1]);
    *(__nv_bfloat162*)(g_ghi + base + 2) = __floats2bfloat162_rn(h[2], h[3]);
    *(__nv_bfloat162*)(g_glo + base) = __floats2bfloat162_rn(l[0], l[1]);
    *(__nv_bfloat162*)(g_glo + base + 2) = __floats2bfloat162_rn(l[2], l[3]);
}

__global__ void k_out(const float* __restrict__ hsrc,
                      const float* __restrict__ bl, const float* __restrict__ Wf,
                      const float* __restrict__ bf, float* __restrict__ out) {
    int warp = (blockIdx.x * blockDim.x + threadIdx.x) >> 5;
    int lane = threadIdx.x & 31;
    if (warp >= Tt) return;
    float acc = 0.f;
    const float* hp = hsrc + (size_t)warp * Hh;
#pragma unroll
    for (int j0 = 0; j0 < Hh; j0 += 32) {
        int j = j0 + lane;
        float v = fmaxf(hp[j] + bl[j], 0.0f);
        acc = fmaf(v, Wf[j], acc);
    }
#pragma unroll
    for (int o = 16; o > 0; o >>= 1) acc += __shfl_xor_sync(0xffffffffu, acc, o);
    if (lane == 0) out[warp] = acc + bf[0];
}

// ---------------- launch ----------------
extern "C" void kernel_launch(void* const* d_in, const int* in_sizes, int n_in,
                              void* d_out, int out_size) {
    const float* x = (const float*)d_in[0];
    const int* ei = (const int*)d_in[1];
    const int* train = (const int*)d_in[2];
    const float* W1 = (const float*)d_in[3];
    const float* W2 = (const float*)d_in[5];
    const float* W3 = (const float*)d_in[7];
    const float* g1 = (const float*)d_in[9];
    const float* be1 = (const float*)d_in[10];
    const float* g2 = (const float*)d_in[11];
    const float* be2 = (const float*)d_in[12];
    const float* g3 = (const float*)d_in[13];
    const float* be3 = (const float*)d_in[14];
    const float* Wl = (const float*)d_in[15];
    const float* bl = (const float*)d_in[16];
    const float* Wf = (const float*)d_in[17];
    const float* bf = (const float*)d_in[18];
    float* out = (float*)d_out;

    const int* row = ei;
    const int* col = ei + Ee;

    float *p_hw, *p_hw2, *p_stats;
    __nv_bfloat16 *p_ahi, *p_alo, *p_ghi, *p_glo, *p_whi, *p_wlo;
    cudaGetSymbolAddress((void**)&p_hw, g_hw);
    cudaGetSymbolAddress((void**)&p_hw2, g_hw2);
    cudaGetSymbolAddress((void**)&p_stats, g_stats4);
    cudaGetSymbolAddress((void**)&p_ahi, g_ahi);
    cudaGetSymbolAddress((void**)&p_alo, g_alo);
    cudaGetSymbolAddress((void**)&p_ghi, g_ghi);
    cudaGetSymbolAddress((void**)&p_glo, g_glo);
    cudaGetSymbolAddress((void**)&p_whi, g_whi);
    cudaGetSymbolAddress((void**)&p_wlo, g_wlo);

    cudaFuncSetAttribute(k_gemm, cudaFuncAttributeMaxDynamicSharedMemorySize, SMEM_GEMM);

    // fork stream + events (host objects; created/destroyed per call)
    cudaStream_t sB;
    cudaStreamCreateWithFlags(&sB, cudaStreamNonBlocking);
    cudaEvent_t evA[3], evB[3];
    for (int i = 0; i < 3; i++) {
        cudaEventCreateWithFlags(&evA[i], cudaEventDisableTiming);
        cudaEventCreateWithFlags(&evB[i], cudaEventDisableTiming);
    }

    // ---- graph preprocessing (stream 0) ----
    k_zero_init<<<(Nn + 255) / 256, 256>>>();
    k_count<<<(Ee + 255) / 256, 256>>>(row);
    k_scan1<<<SCAN_BLOCKS, 256>>>();
    k_scan2<<<1, 256>>>();
    k_scan3<<<SCAN_BLOCKS, 256>>>();
    k_scatter<<<(Ee + 255) / 256, 256>>>(row, col);
    k_wsplit_all<<<(Dd * Hh + 3 * Hh * Hh + 255) / 256, 256>>>(W1, W2, W3, Wl);

    const int AGG1_B = ROWS_H1 / 8;                 // 3136
    const int AGG2_N = Nn - ROWS_H1;                // 24912
    const int AGG2_B = (AGG2_N + 7) / 8;            // 3114
    dim3 grid_h1(2, RB_H1);                         // (2,196)
    dim3 grid_h2(2, RB_ALL - RB_H1);                // (2,195)
    float* st0 = p_stats + 0 * 2 * Hh;
    float* st1 = p_stats + 1 * 2 * Hh;
    float* st2 = p_stats + 2 * 2 * Hh;

    // ---- per-layer staggered pipeline: s0: agg(h1)->gemm(h1); sB: agg(h2)->gemm(h2) ----
#define LAYER(KC, BN, SRC, STIN, GM, BT, WH, WL_, DST, STOUT, LI)                          \
    do {                                                                                   \
        k_agg<KC, BN><<<AGG1_B, 256>>>(0, ROWS_H1, SRC, STIN, GM, BT, p_ahi, p_alo);       \
        cudaEventRecord(evA[LI], 0);                                                       \
        k_gemm<<<grid_h1, 256, SMEM_GEMM>>>(p_ahi, p_alo, WH, WL_, DST, STOUT, Nn, KC, 0); \
        cudaStreamWaitEvent(sB, evA[LI], 0);                                               \
        k_agg<KC, BN><<<AGG2_B, 256, 0, sB>>>(ROWS_H1, AGG2_N, SRC, STIN, GM, BT,          \
                                              p_ahi, p_alo);                               \
        k_gemm<<<grid_h2, 256, SMEM_GEMM, sB>>>(p_ahi, p_alo, WH, WL_, DST, STOUT, Nn, KC, \
                                                RB_H1);                                    \
        cudaEventRecord(evB[LI], sB);                                                      \
        cudaStreamWaitEvent(0, evB[LI], 0);                                                \
    } while (0)

    // layer 1: x -> hw
    LAYER(128, false, x, nullptr, nullptr, nullptr, p_whi, p_wlo, p_hw, st0, 0);
    // layer 2: hw -> hw2
    LAYER(256, true, p_hw, st0, g1, be1, p_whi + 1 * Hh * Hh, p_wlo + 1 * Hh * Hh, p_hw2, st1, 1);
    // layer 3: hw2 -> hw
    LAYER(256, true, p_hw2, st1, g2, be2, p_whi + 2 * Hh * Hh, p_wlo + 2 * Hh * Hh, p_hw, st2, 2);
#undef LAYER

    // ---- head: gather+bn3 from hw; Wl GEMM -> hw2; k_out ----
    k_gather_bn<<<(Tt * 64 + 255) / 256, 256>>>(p_hw, train, st2, g3, be3);
    dim3 head_grid(2, (Tt + 127) / 128);
    k_gemm<<<head_grid, 256, SMEM_GEMM>>>(p_ghi, p_glo, p_whi + 3 * Hh * Hh,
                                          p_wlo + 3 * Hh * Hh, p_hw2, nullptr, Tt, Hh, 0);
    k_out<<<(Tt * 32 + 255) / 256, 256>>>(p_hw2, bl, Wf, bf, out);

    for (int i = 0; i < 3; i++) {
        cudaEventDestroy(evA[i]);
        cudaEventDestroy(evB[i]);
    }
    cudaStreamDestroy(sB);
}